// round 2
// baseline (speedup 1.0000x reference)
#include <cuda_runtime.h>
#include <math.h>

// Problem shape (fixed by setup_inputs)
#define BATCH 256
#define TLEN  1024
#define DDIM  256
#define LOG2PI 1.8378770664093453f

// Main-kernel tiling
#define GB      8                 // batches per block
#define NCHUNK  16                // t-chunks
#define CHUNK   (TLEN / NCHUNK)   // 64
#define BSTRIDE (TLEN * DDIM)     // elements between batches (262144 -> 1MB, fits LDG imm)

// Scratch (no allocations allowed)
__device__ float2 g_tbl[(TLEN - 1) * DDIM];   // (Ad, 1/q) per (t-1, d)   ~2 MB
__device__ float  g_invq0[DDIM];              // 1/var0
__device__ float  g_row[TLEN];                // per-t row sums of log-terms

__device__ __forceinline__ float softplusf(float x) {
    return (x > 20.f) ? x : log1pf(expf(x));
}

// ---------------------------------------------------------------------------
// Kernel 1: precompute tables + per-row log constants; zero the output.
// grid = TLEN blocks, block = DDIM threads
// ---------------------------------------------------------------------------
__global__ void k_precompute(const float* __restrict__ ts,
                             const float* __restrict__ log_kappa,
                             const float* __restrict__ log_sigma,
                             float* __restrict__ out, int out_size) {
    const int t = blockIdx.x;
    const int d = threadIdx.x;

    float kappa = softplusf(log_kappa[d]) + 1e-6f;
    float sigma = softplusf(log_sigma[d]) + 1e-6f;
    float s2 = sigma * sigma;

    float elem;
    if (t == 0) {
        float var0 = fmaxf(s2 / (2.0f * kappa), 1e-10f);
        g_invq0[d] = 1.0f / var0;
        elem = logf(var0) + LOG2PI;
        for (int i = d; i < out_size; i += blockDim.x) out[i] = 0.0f;
    } else {
        float dt = fmaxf(ts[t * DDIM + d] - ts[(t - 1) * DDIM + d], 1e-6f);
        float Ad = expf(-kappa * dt);
        float q  = fmaxf(s2 * (-expm1f(-2.0f * kappa * dt)) / (2.0f * kappa), 1e-10f);
        g_tbl[(t - 1) * DDIM + d] = make_float2(Ad, 1.0f / q);
        elem = logf(q) + LOG2PI;
    }

    // block reduce elem -> g_row[t]
    __shared__ float sm[DDIM];
    sm[d] = elem;
    __syncthreads();
    for (int s = DDIM / 2; s > 0; s >>= 1) {
        if (d < s) sm[d] += sm[d + s];
        __syncthreads();
    }
    if (d == 0) g_row[t] = sm[0];
}

// ---------------------------------------------------------------------------
// Kernel 2: main streaming pass over y + fused constant.
// grid = (BATCH/GB) * NCHUNK blocks, block = DDIM threads.
// Each block: GB batches x one CHUNK of the t-axis; one table load serves
// GB batches. Each block also folds in this chunk's share of the
// batch-independent log-det constant, so no reduce/finalize kernels needed.
// ---------------------------------------------------------------------------
__global__ __launch_bounds__(DDIM)
void k_main(const float* __restrict__ y,
            const float* __restrict__ mu,
            float* __restrict__ out) {
    const int c     = blockIdx.x % NCHUNK;
    const int bbase = (blockIdx.x / NCHUNK) * GB;
    const int d     = threadIdx.x;

    const float mu_d = mu[d];
    const float* __restrict__ yb = y + (size_t)bbase * BSTRIDE + d;

    float acc[GB];
    float prevdf[GB];   // prev - mu

    const int tstart = c * CHUNK;
    const int t0 = (c == 0) ? 1 : tstart;

#pragma unroll
    for (int g = 0; g < GB; g++)
        prevdf[g] = __ldcs(yb + (size_t)(t0 - 1) * DDIM + g * BSTRIDE) - mu_d;

    if (c == 0) {
        float iq0 = g_invq0[d];
#pragma unroll
        for (int g = 0; g < GB; g++)
            acc[g] = prevdf[g] * prevdf[g] * iq0;
    } else {
#pragma unroll
        for (int g = 0; g < GB; g++) acc[g] = 0.0f;
    }

    const int tend = tstart + CHUNK;
    const float2* __restrict__ tbl = g_tbl + d;
#pragma unroll 2
    for (int t = t0; t < tend; ++t) {
        float2 tb = __ldg(&tbl[(t - 1) * DDIM]);
#pragma unroll
        for (int g = 0; g < GB; g++) {
            float ydf = __ldcs(yb + (size_t)t * DDIM + g * BSTRIDE) - mu_d;
            float df  = fmaf(-tb.x, prevdf[g], ydf);
            acc[g]    = fmaf(df * tb.y, df, acc[g]);
            prevdf[g] = ydf;
        }
    }

    // Reduce: warp shuffle per g, then cross-warp in smem.
    const int lane = d & 31;
    const int warp = d >> 5;
    __shared__ float sm[(DDIM / 32) * GB];
#pragma unroll
    for (int g = 0; g < GB; g++) {
        float v = acc[g];
#pragma unroll
        for (int o = 16; o > 0; o >>= 1) v += __shfl_down_sync(0xffffffffu, v, o);
        if (lane == 0) sm[warp * GB + g] = v;
    }
    __syncthreads();

    // Warp 0: chunk constant = sum of this chunk's 64 g_row entries
    // (for c==0 that includes the t=0 var0 row at g_row[0]).
    float chunkC = 0.0f;
    if (warp == 0) {
        float v = g_row[tstart + lane] + g_row[tstart + 32 + lane];
#pragma unroll
        for (int o = 16; o > 0; o >>= 1) v += __shfl_down_sync(0xffffffffu, v, o);
        chunkC = __shfl_sync(0xffffffffu, v, 0);
    }

    if (d < GB) {
        float s = 0.0f;
#pragma unroll
        for (int w = 0; w < DDIM / 32; w++) s += sm[w * GB + d];
        atomicAdd(&out[bbase + d], -0.5f * (s + chunkC));
    }
}

extern "C" void kernel_launch(void* const* d_in, const int* in_sizes, int n_in,
                              void* d_out, int out_size) {
    const float* y  = (const float*)d_in[0];
    const float* ts = (const float*)d_in[1];
    const float* mu = (const float*)d_in[2];
    const float* lk = (const float*)d_in[3];
    const float* ls = (const float*)d_in[4];
    float* out = (float*)d_out;

    k_precompute<<<TLEN, DDIM>>>(ts, lk, ls, out, out_size);
    k_main<<<(BATCH / GB) * NCHUNK, DDIM>>>(y, mu, out);
}

// round 3
// speedup vs baseline: 1.3200x; 1.3200x over previous
#include <cuda_runtime.h>
#include <math.h>

// Problem shape (fixed by setup_inputs)
#define BATCH 256
#define TLEN  1024
#define DDIM  256
#define LOG2PI 1.8378770664093453f

// Main-kernel tiling
#define GBTOT   8                 // batches per block (2 halves x 4 in regs)
#define GBH     4                 // batches per thread (registers)
#define NCHUNK  32                // t-chunks
#define CHUNK   (TLEN / NCHUNK)   // 32
#define BSTRIDE (TLEN * DDIM)     // elements between batches

// Scratch (no allocations allowed)
__device__ float4 g_tbl4[(TLEN - 1) * (DDIM / 2)]; // (Ad,1/q) x 2 d's  ~2MB
__device__ float  g_invq0[DDIM];                   // 1/var0
__device__ float  g_row[TLEN];                     // per-t row sums of log terms

__device__ __forceinline__ float softplusf(float x) {
    return (x > 20.f) ? x : log1pf(expf(x));
}

// ---------------------------------------------------------------------------
// Kernel 1: precompute tables + per-row log constants; zero the output.
// grid = TLEN blocks, block = DDIM threads
// ---------------------------------------------------------------------------
__global__ void k_precompute(const float* __restrict__ ts,
                             const float* __restrict__ log_kappa,
                             const float* __restrict__ log_sigma,
                             float* __restrict__ out, int out_size) {
    const int t = blockIdx.x;
    const int d = threadIdx.x;

    float kappa = softplusf(log_kappa[d]) + 1e-6f;
    float sigma = softplusf(log_sigma[d]) + 1e-6f;
    float s2 = sigma * sigma;

    float elem;
    if (t == 0) {
        float var0 = fmaxf(s2 / (2.0f * kappa), 1e-10f);
        g_invq0[d] = 1.0f / var0;
        elem = logf(var0) + LOG2PI;
        for (int i = d; i < out_size; i += blockDim.x) out[i] = 0.0f;
    } else {
        float dt = fmaxf(ts[t * DDIM + d] - ts[(t - 1) * DDIM + d], 1e-6f);
        float Ad = expf(-kappa * dt);
        float q  = fmaxf(s2 * (-expm1f(-2.0f * kappa * dt)) / (2.0f * kappa), 1e-10f);
        // float2 view index (t-1)*256 + d lands at float4[(t-1)*128 + d/2].{xy|zw}
        ((float2*)g_tbl4)[(t - 1) * DDIM + d] = make_float2(Ad, 1.0f / q);
        elem = logf(q) + LOG2PI;
    }

    __shared__ float sm[DDIM];
    sm[d] = elem;
    __syncthreads();
    for (int s = DDIM / 2; s > 0; s >>= 1) {
        if (d < s) sm[d] += sm[d + s];
        __syncthreads();
    }
    if (d == 0) g_row[t] = sm[0];
}

// ---------------------------------------------------------------------------
// Kernel 2: main streaming pass over y + fused constant.
// grid = (BATCH/GBTOT)*NCHUNK = 1024 blocks, block = 256 threads.
// Thread layout: dv = tid&127 covers d = {2dv, 2dv+1}; h = tid>>7 selects a
// half handling batches [bbase+4h, bbase+4h+4). y loads are LDG.64, table
// loads LDG.128; one table load serves 8 batches (2 halves broadcast in L1).
// Each block folds in its chunk's share of the log-det constant.
// ---------------------------------------------------------------------------
__global__ __launch_bounds__(256)
void k_main(const float* __restrict__ y,
            const float* __restrict__ mu,
            float* __restrict__ out) {
    const int c     = blockIdx.x & (NCHUNK - 1);
    const int bbase = (blockIdx.x >> 5) * GBTOT;
    const int tid   = threadIdx.x;
    const int dv    = tid & 127;
    const int h     = tid >> 7;

    const float2 mu2 = *(const float2*)(mu + 2 * dv);
    const float* __restrict__ yb =
        y + (size_t)(bbase + h * GBH) * BSTRIDE + 2 * dv;

    float  acc[GBH];
    float2 prevdf[GBH];

    const int tstart = c * CHUNK;
    const int t0 = (c == 0) ? 1 : tstart;

#pragma unroll
    for (int g = 0; g < GBH; g++) {
        float2 p = __ldcs((const float2*)(yb + (size_t)(t0 - 1) * DDIM + g * BSTRIDE));
        prevdf[g] = make_float2(p.x - mu2.x, p.y - mu2.y);
    }

    if (c == 0) {
        float2 iq0 = *(const float2*)(g_invq0 + 2 * dv);
#pragma unroll
        for (int g = 0; g < GBH; g++)
            acc[g] = prevdf[g].x * prevdf[g].x * iq0.x
                   + prevdf[g].y * prevdf[g].y * iq0.y;
    } else {
#pragma unroll
        for (int g = 0; g < GBH; g++) acc[g] = 0.0f;
    }

    const int tend = tstart + CHUNK;
    const float4* __restrict__ tbl = g_tbl4 + dv;
#pragma unroll 2
    for (int t = t0; t < tend; ++t) {
        float4 tb = __ldg(&tbl[(t - 1) * (DDIM / 2)]);
#pragma unroll
        for (int g = 0; g < GBH; g++) {
            float2 yv = __ldcs((const float2*)(yb + (size_t)t * DDIM + g * BSTRIDE));
            float ydx = yv.x - mu2.x;
            float ydy = yv.y - mu2.y;
            float dfx = fmaf(-tb.x, prevdf[g].x, ydx);
            float dfy = fmaf(-tb.z, prevdf[g].y, ydy);
            acc[g] = fmaf(dfx * tb.y, dfx, acc[g]);
            acc[g] = fmaf(dfy * tb.w, dfy, acc[g]);
            prevdf[g] = make_float2(ydx, ydy);
        }
    }

    // Reduce: warp shuffle per g, cross-warp via smem.
    // Warps 0-3 belong to half 0, warps 4-7 to half 1.
    const int lane = tid & 31;
    const int warp = tid >> 5;
    __shared__ float sm[8][GBH];
#pragma unroll
    for (int g = 0; g < GBH; g++) {
        float v = acc[g];
#pragma unroll
        for (int o = 16; o > 0; o >>= 1) v += __shfl_down_sync(0xffffffffu, v, o);
        if (lane == 0) sm[warp][g] = v;
    }
    __syncthreads();

    // Chunk constant: sum of this chunk's CHUNK(=32) g_row entries (warp 0).
    float chunkC = 0.0f;
    if (warp == 0) {
        float v = g_row[tstart + lane];
#pragma unroll
        for (int o = 16; o > 0; o >>= 1) v += __shfl_down_sync(0xffffffffu, v, o);
        chunkC = __shfl_sync(0xffffffffu, v, 0);
    }

    if (tid < GBTOT) {
        int h2 = tid >> 2;      // which half
        int g  = tid & 3;       // which batch within half
        float s = sm[h2 * 4 + 0][g] + sm[h2 * 4 + 1][g]
                + sm[h2 * 4 + 2][g] + sm[h2 * 4 + 3][g];
        atomicAdd(&out[bbase + h2 * GBH + g], -0.5f * (s + chunkC));
    }
}

extern "C" void kernel_launch(void* const* d_in, const int* in_sizes, int n_in,
                              void* d_out, int out_size) {
    const float* y  = (const float*)d_in[0];
    const float* ts = (const float*)d_in[1];
    const float* mu = (const float*)d_in[2];
    const float* lk = (const float*)d_in[3];
    const float* ls = (const float*)d_in[4];
    float* out = (float*)d_out;

    k_precompute<<<TLEN, DDIM>>>(ts, lk, ls, out, out_size);
    k_main<<<(BATCH / GBTOT) * NCHUNK, 256>>>(y, mu, out);
}

// round 4
// speedup vs baseline: 1.6316x; 1.2361x over previous
#include <cuda_runtime.h>
#include <math.h>

// Problem shape (fixed by setup_inputs)
#define BATCH 256
#define TLEN  1024
#define DDIM  256
#define LOG2PI 1.8378770664093453f

// Main-kernel tiling
#define GBTOT   8                 // batches per block (2 halves x 4)
#define GBH     4                 // batches per thread half
#define NCHUNK  32                // t-chunks
#define CHUNK   (TLEN / NCHUNK)   // 32
#define BSTRIDE (TLEN * DDIM)     // elements between batches (1MB)

// Table: 3 SoA sections of (TLEN-1)*DDIM floats each, one base pointer so
// section offsets fold into LDG immediates.
#define SEC    ((TLEN - 1) * DDIM)
#define SEC_A  0
#define SEC_R  SEC
#define SEC_C  (2 * SEC)
__device__ float g_tabf[3 * SEC];   // A=exp(-k dt), R=1/sqrt(q), C=-mu*(1-A)*R
__device__ float g_r0[DDIM];        // 1/sqrt(var0)
__device__ float g_c0[DDIM];        // -mu/sqrt(var0)
__device__ float g_row[TLEN];       // per-t row sums of log q + LOG2PI

__device__ __forceinline__ float softplusf(float x) {
    return (x > 20.f) ? x : log1pf(expf(x));
}

// ---------------------------------------------------------------------------
// Kernel 1: precompute table + per-row log constants; zero the output.
// grid = TLEN blocks, block = DDIM threads
// ---------------------------------------------------------------------------
__global__ void k_precompute(const float* __restrict__ ts,
                             const float* __restrict__ log_kappa,
                             const float* __restrict__ log_sigma,
                             const float* __restrict__ mu,
                             float* __restrict__ out, int out_size) {
    const int t = blockIdx.x;
    const int d = threadIdx.x;

    float kappa = softplusf(log_kappa[d]) + 1e-6f;
    float sigma = softplusf(log_sigma[d]) + 1e-6f;
    float s2 = sigma * sigma;
    float mu_d = mu[d];

    float elem;
    if (t == 0) {
        float var0 = fmaxf(s2 / (2.0f * kappa), 1e-10f);
        float r0 = 1.0f / sqrtf(var0);
        g_r0[d] = r0;
        g_c0[d] = -mu_d * r0;
        elem = logf(var0) + LOG2PI;
        for (int i = d; i < out_size; i += blockDim.x) out[i] = 0.0f;
    } else {
        float dt = fmaxf(ts[t * DDIM + d] - ts[(t - 1) * DDIM + d], 1e-6f);
        float Ad = expf(-kappa * dt);
        float q  = fmaxf(s2 * (-expm1f(-2.0f * kappa * dt)) / (2.0f * kappa), 1e-10f);
        float R  = 1.0f / sqrtf(q);
        int idx = (t - 1) * DDIM + d;
        g_tabf[SEC_A + idx] = Ad;
        g_tabf[SEC_R + idx] = R;
        g_tabf[SEC_C + idx] = -mu_d * (1.0f - Ad) * R;
        elem = logf(q) + LOG2PI;
    }

    __shared__ float sm[DDIM];
    sm[d] = elem;
    __syncthreads();
    for (int s = DDIM / 2; s > 0; s >>= 1) {
        if (d < s) sm[d] += sm[d + s];
        __syncthreads();
    }
    if (d == 0) g_row[t] = sm[0];
}

// ---------------------------------------------------------------------------
// Kernel 2: main streaming pass. grid = 1024 blocks, block = 256 threads.
// dv = tid&127 covers d = {2dv, 2dv+1}; h = tid>>7 handles 4 batches.
// 4-deep t-window: ALL loads (16 y LDG.64 + 12 table LDG.64) front-batched,
// then pure FMA. Inner math: z = fma(fma(-A,prev,y), R, C); acc = fma(z,z,acc).
// Each block folds in its chunk's share of the log-det constant.
// ---------------------------------------------------------------------------
__global__ __launch_bounds__(256, 3)
void k_main(const float* __restrict__ y, float* __restrict__ out) {
    const int c     = blockIdx.x & (NCHUNK - 1);
    const int bbase = (blockIdx.x >> 5) * GBTOT;
    const int tid   = threadIdx.x;
    const int dv    = tid & 127;
    const int h     = tid >> 7;

    const float* __restrict__ yb =
        y + (size_t)(bbase + h * GBH) * BSTRIDE + 2 * dv;

    const int tstart = c * CHUNK;
    const int t0   = (c == 0) ? 1 : tstart;
    const int tend = tstart + CHUNK;

    float2 prev[GBH];
    float  acc[GBH];
#pragma unroll
    for (int g = 0; g < GBH; g++)
        prev[g] = *(const float2*)(yb + (size_t)(t0 - 1) * DDIM + g * BSTRIDE);

    if (c == 0) {
        float2 r0 = *(const float2*)(g_r0 + 2 * dv);
        float2 c0 = *(const float2*)(g_c0 + 2 * dv);
#pragma unroll
        for (int g = 0; g < GBH; g++) {
            float zx = fmaf(prev[g].x, r0.x, c0.x);
            float zy = fmaf(prev[g].y, r0.y, c0.y);
            acc[g] = zx * zx + zy * zy;
        }
    } else {
#pragma unroll
        for (int g = 0; g < GBH; g++) acc[g] = 0.0f;
    }

    const float* __restrict__ tb = g_tabf + 2 * dv;

    int t = t0;
    for (; t + 3 < tend; t += 4) {
        // ---- front-batched loads: 16 y (DRAM) then 12 table (L2/L1) ----
        float2 yv[4][GBH];
        const float* yt = yb + (size_t)t * DDIM;
#pragma unroll
        for (int u = 0; u < 4; u++)
#pragma unroll
            for (int g = 0; g < GBH; g++)
                yv[u][g] = __ldcs((const float2*)(yt + u * DDIM + g * BSTRIDE));

        float2 A[4], R[4], Cc[4];
        const float* tt = tb + (size_t)(t - 1) * DDIM;
#pragma unroll
        for (int u = 0; u < 4; u++) {
            A[u]  = *(const float2*)(tt + u * DDIM + SEC_A);
            R[u]  = *(const float2*)(tt + u * DDIM + SEC_R);
            Cc[u] = *(const float2*)(tt + u * DDIM + SEC_C);
        }

        // ---- compute ----
#pragma unroll
        for (int u = 0; u < 4; u++)
#pragma unroll
            for (int g = 0; g < GBH; g++) {
                float xx = fmaf(-A[u].x, prev[g].x, yv[u][g].x);
                float xy = fmaf(-A[u].y, prev[g].y, yv[u][g].y);
                float zx = fmaf(xx, R[u].x, Cc[u].x);
                float zy = fmaf(xy, R[u].y, Cc[u].y);
                acc[g] = fmaf(zx, zx, acc[g]);
                acc[g] = fmaf(zy, zy, acc[g]);
                prev[g] = yv[u][g];
            }
    }
    // remainder (only for c==0: 3 iterations)
    for (; t < tend; ++t) {
        const float* tt = tb + (size_t)(t - 1) * DDIM;
        float2 A  = *(const float2*)(tt + SEC_A);
        float2 R  = *(const float2*)(tt + SEC_R);
        float2 Cc = *(const float2*)(tt + SEC_C);
#pragma unroll
        for (int g = 0; g < GBH; g++) {
            float2 yv = __ldcs((const float2*)(yb + (size_t)t * DDIM + g * BSTRIDE));
            float xx = fmaf(-A.x, prev[g].x, yv.x);
            float xy = fmaf(-A.y, prev[g].y, yv.y);
            float zx = fmaf(xx, R.x, Cc.x);
            float zy = fmaf(xy, R.y, Cc.y);
            acc[g] = fmaf(zx, zx, acc[g]);
            acc[g] = fmaf(zy, zy, acc[g]);
            prev[g] = yv;
        }
    }

    // ---- reduce: warp shuffle per g, cross-warp via smem ----
    const int lane = tid & 31;
    const int warp = tid >> 5;
    __shared__ float sm[8][GBH];
#pragma unroll
    for (int g = 0; g < GBH; g++) {
        float v = acc[g];
#pragma unroll
        for (int o = 16; o > 0; o >>= 1) v += __shfl_down_sync(0xffffffffu, v, o);
        if (lane == 0) sm[warp][g] = v;
    }
    __syncthreads();

    // chunk constant: sum of this chunk's 32 g_row entries (warp 0)
    float chunkC = 0.0f;
    if (warp == 0) {
        float v = g_row[tstart + lane];
#pragma unroll
        for (int o = 16; o > 0; o >>= 1) v += __shfl_down_sync(0xffffffffu, v, o);
        chunkC = __shfl_sync(0xffffffffu, v, 0);
    }

    if (tid < GBTOT) {
        int h2 = tid >> 2;
        int g  = tid & 3;
        float s = sm[h2 * 4 + 0][g] + sm[h2 * 4 + 1][g]
                + sm[h2 * 4 + 2][g] + sm[h2 * 4 + 3][g];
        atomicAdd(&out[bbase + h2 * GBH + g], -0.5f * (s + chunkC));
    }
}

extern "C" void kernel_launch(void* const* d_in, const int* in_sizes, int n_in,
                              void* d_out, int out_size) {
    const float* y  = (const float*)d_in[0];
    const float* ts = (const float*)d_in[1];
    const float* mu = (const float*)d_in[2];
    const float* lk = (const float*)d_in[3];
    const float* ls = (const float*)d_in[4];
    float* out = (float*)d_out;

    k_precompute<<<TLEN, DDIM>>>(ts, lk, ls, mu, out, out_size);
    k_main<<<(BATCH / GBTOT) * NCHUNK, 256>>>(y, out);
}

// round 5
// speedup vs baseline: 1.6337x; 1.0012x over previous
#include <cuda_runtime.h>
#include <math.h>

// Problem shape (fixed by setup_inputs)
#define BATCH 256
#define TLEN  1024
#define DDIM  256
#define LOG2PI 1.8378770664093453f

// Main-kernel tiling
#define GBTOT   8                 // batches per block (2 halves x 4)
#define GBH     4                 // batches per thread half
#define NCHUNK  32                // t-chunks
#define CHUNK   (TLEN / NCHUNK)   // 32
#define BSTRIDE (TLEN * DDIM)     // elements between batches (1MB)

// Table: 3 SoA sections of (TLEN-1)*DDIM floats each, one base pointer so
// section offsets fold into LDG immediates.
#define SEC    ((TLEN - 1) * DDIM)
#define SEC_A  0
#define SEC_R  SEC
#define SEC_C  (2 * SEC)
__device__ float g_tabf[3 * SEC];   // A=exp(-k dt), R=1/sqrt(q), C=-mu*(1-A)*R
__device__ float g_r0[DDIM];        // 1/sqrt(var0)
__device__ float g_c0[DDIM];        // -mu/sqrt(var0)
__device__ float g_row[TLEN];       // per-t row sums of log q + LOG2PI

__device__ __forceinline__ float softplusf(float x) {
    return (x > 20.f) ? x : log1pf(expf(x));
}

// ---------------------------------------------------------------------------
// Kernel 1: precompute table + per-row log constants; zero the output.
// grid = TLEN blocks, block = DDIM threads
// ---------------------------------------------------------------------------
__global__ void k_precompute(const float* __restrict__ ts,
                             const float* __restrict__ log_kappa,
                             const float* __restrict__ log_sigma,
                             const float* __restrict__ mu,
                             float* __restrict__ out, int out_size) {
    const int t = blockIdx.x;
    const int d = threadIdx.x;

    float kappa = softplusf(log_kappa[d]) + 1e-6f;
    float sigma = softplusf(log_sigma[d]) + 1e-6f;
    float s2 = sigma * sigma;
    float mu_d = mu[d];

    float elem;
    if (t == 0) {
        float var0 = fmaxf(s2 / (2.0f * kappa), 1e-10f);
        float r0 = 1.0f / sqrtf(var0);
        g_r0[d] = r0;
        g_c0[d] = -mu_d * r0;
        elem = logf(var0) + LOG2PI;
        for (int i = d; i < out_size; i += blockDim.x) out[i] = 0.0f;
    } else {
        float dt = fmaxf(ts[t * DDIM + d] - ts[(t - 1) * DDIM + d], 1e-6f);
        float Ad = expf(-kappa * dt);
        float q  = fmaxf(s2 * (-expm1f(-2.0f * kappa * dt)) / (2.0f * kappa), 1e-10f);
        float R  = 1.0f / sqrtf(q);
        int idx = (t - 1) * DDIM + d;
        g_tabf[SEC_A + idx] = Ad;
        g_tabf[SEC_R + idx] = R;
        g_tabf[SEC_C + idx] = -mu_d * (1.0f - Ad) * R;
        elem = logf(q) + LOG2PI;
    }

    __shared__ float sm[DDIM];
    sm[d] = elem;
    __syncthreads();
    for (int s = DDIM / 2; s > 0; s >>= 1) {
        if (d < s) sm[d] += sm[d + s];
        __syncthreads();
    }
    if (d == 0) g_row[t] = sm[0];
}

// ---------------------------------------------------------------------------
// Kernel 2: main streaming pass. grid = 1024 blocks, block = 256 threads.
// dv = tid&127 covers d = {2dv, 2dv+1}; h = tid>>7 handles 4 batches.
// 4-deep t-window: all 16 y LDG.64 front-batched (covers DRAM latency);
// table loads are just-in-time per step (L1/L2 hits, cheap) to keep regs
// under the 64-reg / 4-blocks-per-SM budget.
// Inner math: z = fma(fma(-A,prev,y), R, C); acc = fma(z,z,acc).
// ---------------------------------------------------------------------------
__global__ __launch_bounds__(256, 4)
void k_main(const float* __restrict__ y, float* __restrict__ out) {
    const int c     = blockIdx.x & (NCHUNK - 1);
    const int bbase = (blockIdx.x >> 5) * GBTOT;
    const int tid   = threadIdx.x;
    const int dv    = tid & 127;
    const int h     = tid >> 7;

    const float* __restrict__ yb =
        y + (size_t)(bbase + h * GBH) * BSTRIDE + 2 * dv;

    const int tstart = c * CHUNK;
    const int t0   = (c == 0) ? 1 : tstart;
    const int tend = tstart + CHUNK;

    float2 prev[GBH];
    float  acc[GBH];
#pragma unroll
    for (int g = 0; g < GBH; g++)
        prev[g] = *(const float2*)(yb + (size_t)(t0 - 1) * DDIM + g * BSTRIDE);

    if (c == 0) {
        float2 r0 = *(const float2*)(g_r0 + 2 * dv);
        float2 c0 = *(const float2*)(g_c0 + 2 * dv);
#pragma unroll
        for (int g = 0; g < GBH; g++) {
            float zx = fmaf(prev[g].x, r0.x, c0.x);
            float zy = fmaf(prev[g].y, r0.y, c0.y);
            acc[g] = zx * zx + zy * zy;
        }
    } else {
#pragma unroll
        for (int g = 0; g < GBH; g++) acc[g] = 0.0f;
    }

    const float* __restrict__ tb = g_tabf + 2 * dv;

    int t = t0;
    for (; t + 3 < tend; t += 4) {
        // ---- front-batched y loads: 16 LDG.64 back-to-back (DRAM MLP) ----
        float2 yv[4][GBH];
        const float* yt = yb + (size_t)t * DDIM;
#pragma unroll
        for (int u = 0; u < 4; u++)
#pragma unroll
            for (int g = 0; g < GBH; g++)
                yv[u][g] = __ldcs((const float2*)(yt + u * DDIM + g * BSTRIDE));

        // ---- per-step table loads (L1/L2 hits) + compute ----
        const float* tt = tb + (size_t)(t - 1) * DDIM;
#pragma unroll
        for (int u = 0; u < 4; u++) {
            float2 A  = __ldg((const float2*)(tt + u * DDIM + SEC_A));
            float2 R  = __ldg((const float2*)(tt + u * DDIM + SEC_R));
            float2 Cc = __ldg((const float2*)(tt + u * DDIM + SEC_C));
#pragma unroll
            for (int g = 0; g < GBH; g++) {
                float xx = fmaf(-A.x, prev[g].x, yv[u][g].x);
                float xy = fmaf(-A.y, prev[g].y, yv[u][g].y);
                float zx = fmaf(xx, R.x, Cc.x);
                float zy = fmaf(xy, R.y, Cc.y);
                acc[g] = fmaf(zx, zx, acc[g]);
                acc[g] = fmaf(zy, zy, acc[g]);
                prev[g] = yv[u][g];
            }
        }
    }
    // remainder (only for c==0: 3 iterations)
    for (; t < tend; ++t) {
        const float* tt = tb + (size_t)(t - 1) * DDIM;
        float2 A  = __ldg((const float2*)(tt + SEC_A));
        float2 R  = __ldg((const float2*)(tt + SEC_R));
        float2 Cc = __ldg((const float2*)(tt + SEC_C));
#pragma unroll
        for (int g = 0; g < GBH; g++) {
            float2 yv = __ldcs((const float2*)(yb + (size_t)t * DDIM + g * BSTRIDE));
            float xx = fmaf(-A.x, prev[g].x, yv.x);
            float xy = fmaf(-A.y, prev[g].y, yv.y);
            float zx = fmaf(xx, R.x, Cc.x);
            float zy = fmaf(xy, R.y, Cc.y);
            acc[g] = fmaf(zx, zx, acc[g]);
            acc[g] = fmaf(zy, zy, acc[g]);
            prev[g] = yv;
        }
    }

    // ---- reduce: warp shuffle per g, cross-warp via smem ----
    const int lane = tid & 31;
    const int warp = tid >> 5;
    __shared__ float sm[8][GBH];
#pragma unroll
    for (int g = 0; g < GBH; g++) {
        float v = acc[g];
#pragma unroll
        for (int o = 16; o > 0; o >>= 1) v += __shfl_down_sync(0xffffffffu, v, o);
        if (lane == 0) sm[warp][g] = v;
    }
    __syncthreads();

    // chunk constant: sum of this chunk's 32 g_row entries (warp 0)
    float chunkC = 0.0f;
    if (warp == 0) {
        float v = g_row[tstart + lane];
#pragma unroll
        for (int o = 16; o > 0; o >>= 1) v += __shfl_down_sync(0xffffffffu, v, o);
        chunkC = __shfl_sync(0xffffffffu, v, 0);
    }

    if (tid < GBTOT) {
        int h2 = tid >> 2;
        int g  = tid & 3;
        float s = sm[h2 * 4 + 0][g] + sm[h2 * 4 + 1][g]
                + sm[h2 * 4 + 2][g] + sm[h2 * 4 + 3][g];
        atomicAdd(&out[bbase + h2 * GBH + g], -0.5f * (s + chunkC));
    }
}

extern "C" void kernel_launch(void* const* d_in, const int* in_sizes, int n_in,
                              void* d_out, int out_size) {
    const float* y  = (const float*)d_in[0];
    const float* ts = (const float*)d_in[1];
    const float* mu = (const float*)d_in[2];
    const float* lk = (const float*)d_in[3];
    const float* ls = (const float*)d_in[4];
    float* out = (float*)d_out;

    k_precompute<<<TLEN, DDIM>>>(ts, lk, ls, mu, out, out_size);
    k_main<<<(BATCH / GBTOT) * NCHUNK, 256>>>(y, out);
}